// round 13
// baseline (speedup 1.0000x reference)
#include <cuda_runtime.h>
#include <stdint.h>

// Lovasz-Softmax, N=8, C=19, H=W=512.
// R13 = R12 with a LEGAL handshake (R12 deadlocked on divergent bar.sync /
// bar.arrive inside warp 0). Now: whole warp 0 executes BAR_SYNC, warps
// 1-31 execute BAR_ARRIVE (warp-uniform); thread 0 issues after the sync;
// release condition (ch + NSLOT < nch) computed identically in all threads.
// NBINS=256, 1024 threads (32 warps), 6-slot x 32KB TMA chunk ring.

#define NCLS   19
#define NBINS  256
#define CUTBIN 64                  // e < 1/4 cut
#define HWSZ   (512 * 512)
#define NPIX   (8 * HWSZ)
#define NBLK   148
#define NTHR_H 1024

#define TILE_PAIRS 1024
#define NTILES     (NPIX / 2 / TILE_PAIRS)   // 1024
#define ROW_B      8192            // 1024 pairs * 8B
#define CHUNK_ROWS 4
#define CHUNK_B    (CHUNK_ROWS * ROW_B)      // 32768
#define NSLOT      6
#define NCHPT      5               // chunks per tile (labels + 19 classes)

#define HIST_WORDS (NCLS * NBINS + 64)       // 4928
#define HIST_B     (HIST_WORDS * 4)          // 19712
#define SMEM_TOTAL (HIST_B + NSLOT * CHUNK_B) // 216320

#define H_MAG  0x6600u             // fp16 bits of 1536.0 (1.5*2^10)
#define H_MAG2 0x66006600u
#define H_CUT  (H_MAG + CUTBIN)

#define F_L2E  1.4426950408889634f
#define F_MG   12582912.0f         // 1.5 * 2^23
#define F_C4   9.61812910e-3f
#define F_C3   5.55041087e-2f
#define F_C2   2.40226507e-1f
#define F_C1   6.93147181e-1f

typedef unsigned long long u64;

__device__ uint32_t g_part[NBLK * NCLS * NBINS];   // ~2.9 MB
__device__ uint32_t g_cnt[NCLS * NBINS];
__device__ uint32_t g_fg [NCLS * NBINS];

// ---- packed f32x2 helpers (PTX-only) ----
__device__ __forceinline__ u64 pk(float a, float b) {
    u64 r; asm("mov.b64 %0,{%1,%2};" : "=l"(r) : "f"(a), "f"(b)); return r;
}
__device__ __forceinline__ void upk(u64 v, float& a, float& b) {
    asm("mov.b64 {%0,%1},%2;" : "=f"(a), "=f"(b) : "l"(v));
}
__device__ __forceinline__ u64 f2fma(u64 a, u64 b, u64 c) {
    u64 r; asm("fma.rn.f32x2 %0,%1,%2,%3;" : "=l"(r) : "l"(a), "l"(b), "l"(c));
    return r;
}
__device__ __forceinline__ u64 dup2(float a) { return pk(a, a); }
__device__ __forceinline__ float rcp_fast(float x) {
    float r; asm("rcp.approx.f32 %0,%1;" : "=f"(r) : "f"(x)); return r;
}
__device__ __forceinline__ uint32_t s2u(const void* p) {
    uint32_t a;
    asm("{ .reg .u64 t; cvta.to.shared.u64 t, %1; cvt.u32.u64 %0, t; }"
        : "=r"(a) : "l"(p));
    return a;
}

__device__ __forceinline__ void mbar_init(uint32_t a, uint32_t cnt) {
    asm volatile("mbarrier.init.shared.b64 [%0], %1;" :: "r"(a), "r"(cnt)
                 : "memory");
}
__device__ __forceinline__ void mbar_expect(uint32_t a, uint32_t bytes) {
    asm volatile("mbarrier.arrive.expect_tx.shared.b64 _, [%0], %1;"
                 :: "r"(a), "r"(bytes) : "memory");
}
__device__ __forceinline__ void bulk_cp(uint32_t dst, const void* src,
                                        uint32_t bytes, uint32_t mbar) {
    asm volatile(
        "cp.async.bulk.shared::cta.global.mbarrier::complete_tx::bytes "
        "[%0], [%1], %2, [%3];"
        :: "r"(dst), "l"((u64)src), "r"(bytes), "r"(mbar) : "memory");
}
__device__ __forceinline__ void mbar_wait(uint32_t a, uint32_t parity) {
    asm volatile(
        "{\n\t"
        ".reg .pred P;\n\t"
        "W_%=:\n\t"
        "mbarrier.try_wait.parity.acquire.cta.shared::cta.b64 P, [%0], %1, 0x989680;\n\t"
        "@P bra.uni D_%=;\n\t"
        "bra.uni W_%=;\n\t"
        "D_%=:\n\t"
        "}"
        :: "r"(a), "r"(parity) : "memory");
}
#define BAR_ARRIVE(id) \
    asm volatile("bar.arrive %0, %1;" :: "r"(id), "r"(NTHR_H) : "memory")
#define BAR_SYNC(id) \
    asm volatile("bar.sync %0, %1;"   :: "r"(id), "r"(NTHR_H) : "memory")

// Packed exp of one row element -> fp16x2 (lo = pixel a), accumulate sums.
__device__ __forceinline__ void exp_row(const u64* row, int tid,
                                        float& sa, float& sb, uint32_t& out,
                                        u64 LOG2E, u64 MG, u64 NONE,
                                        u64 C4, u64 C3, u64 C2, u64 C1, u64 C0) {
    u64 xv = row[tid];                         // LDS.64, conflict-free
    u64 fm = f2fma(xv, LOG2E, MG);
    u64 nf = f2fma(fm, NONE, MG);              // -round(t)
    u64 f  = f2fma(xv, LOG2E, nf);
    u64 r  = f2fma(C4, f, C3);
    r = f2fma(r, f, C2);
    r = f2fma(r, f, C1);
    r = f2fma(r, f, C0);
    float fm0, fm1, r0, r1;
    upk(fm, fm0, fm1);
    upk(r, r0, r1);
    float e0 = __int_as_float(__float_as_int(r0) + __float_as_int(fm0) * 8388608);
    float e1 = __int_as_float(__float_as_int(r1) + __float_as_int(fm1) * 8388608);
    sa += e0;
    sb += e1;
    asm("cvt.rn.f16x2.f32 %0,%1,%2;" : "=r"(out) : "f"(e1), "f"(e0));
}

__device__ __forceinline__ void issue_chunk(
    uint32_t slot_addr, uint32_t mbar,
    const float* logits, const int* labels, int tile, int k) {
    mbar_expect(mbar, CHUNK_B);
    int p0 = tile * (TILE_PAIRS * 2);
    int n  = p0 >> 18;
    int hw = p0 & (HWSZ - 1);
#pragma unroll
    for (int j = 0; j < CHUNK_ROWS; j++) {
        int r = 4 * k + j;
        const void* src = (r == 0)
            ? (const void*)(labels + p0)
            : (const void*)(logits + ((size_t)n * NCLS + (r - 1)) * HWSZ + hw);
        bulk_cp(slot_addr + j * ROW_B, src, ROW_B, mbar);
    }
}

extern __shared__ uint32_t sh[];   // hist | 6 x 32KB ring

__global__ __launch_bounds__(NTHR_H, 1) void hist_kernel(
    const float* __restrict__ logits, const int* __restrict__ labels,
    float* __restrict__ d_out) {
    __shared__ __align__(8) u64 mb_full[NSLOT];
    int tid  = threadIdx.x;
    int warp = tid >> 5;
    int bid  = blockIdx.x;
    char* smem = (char*)sh;

    uint32_t mba[NSLOT];
#pragma unroll
    for (int s = 0; s < NSLOT; s++) mba[s] = s2u(&mb_full[s]);
    uint32_t ring_u32 = s2u(smem + HIST_B);

    if (bid == 0 && tid == 0) *d_out = 0.0f;
    if (tid == 0)
#pragma unroll
        for (int s = 0; s < NSLOT; s++) mbar_init(mba[s], 1);
    {
        uint4 z = make_uint4(0, 0, 0, 0);
        uint4* s4 = (uint4*)sh;
        for (int i = tid; i < HIST_WORDS / 4; i += NTHR_H) s4[i] = z;
    }
    __syncthreads();   // mbarrier init + hist zero visible

    const u64 LOG2E = dup2(F_L2E);
    const u64 MG    = dup2(F_MG);
    const u64 NONE  = dup2(-1.0f);
    const u64 C4 = dup2(F_C4);
    const u64 C3 = dup2(F_C3);
    const u64 C2 = dup2(F_C2);
    const u64 C1 = dup2(F_C1);
    const u64 C0 = dup2(1.0f);
    const uint32_t MG16 = H_MAG2;

    // Chunk bookkeeping: identical in every thread.
    int ntile = (NTILES - bid + NBLK - 1) / NBLK;
    int nch   = ntile * NCHPT;                // >= 30, so prologue of 6 is safe
    int ch    = 0;                            // consumed-chunk counter

    // Producer cursors (meaningful in thread 0 only).
    int p_tile = bid, p_k = 0, p_slot = 0;
    if (tid == 0) {
#pragma unroll
        for (int i = 0; i < NSLOT; i++) {
            issue_chunk(ring_u32 + p_slot * CHUNK_B, mba[p_slot],
                        logits, labels, p_tile, p_k);
            if (++p_k == NCHPT) { p_k = 0; p_tile += NBLK; }
            if (++p_slot == NSLOT) p_slot = 0;
        }
    }

    int lslot = 0, lphase = 0;
    for (int t = bid; t < NTILES; t += NBLK) {
        uint32_t eb[NCLS];
        float sa = 0.0f, sb = 0.0f;
        int2 lab;

#pragma unroll
        for (int k = 0; k < NCHPT; k++) {
            mbar_wait(mba[lslot], lphase);
            const u64* rows = (const u64*)(smem + HIST_B + lslot * CHUNK_B);
            if (k == 0) {
                lab = ((const int2*)rows)[tid];
                exp_row(rows + 1 * 1024, tid, sa, sb, eb[0],
                        LOG2E, MG, NONE, C4, C3, C2, C1, C0);
                exp_row(rows + 2 * 1024, tid, sa, sb, eb[1],
                        LOG2E, MG, NONE, C4, C3, C2, C1, C0);
                exp_row(rows + 3 * 1024, tid, sa, sb, eb[2],
                        LOG2E, MG, NONE, C4, C3, C2, C1, C0);
            } else {
                const int c0 = 4 * k - 1;
                exp_row(rows + 0 * 1024, tid, sa, sb, eb[c0 + 0],
                        LOG2E, MG, NONE, C4, C3, C2, C1, C0);
                exp_row(rows + 1 * 1024, tid, sa, sb, eb[c0 + 1],
                        LOG2E, MG, NONE, C4, C3, C2, C1, C0);
                exp_row(rows + 2 * 1024, tid, sa, sb, eb[c0 + 2],
                        LOG2E, MG, NONE, C4, C3, C2, C1, C0);
                exp_row(rows + 3 * 1024, tid, sa, sb, eb[c0 + 3],
                        LOG2E, MG, NONE, C4, C3, C2, C1, C0);
            }

            // Release slot + reissue. Condition uniform across the CTA;
            // barrier instruction uniform within every warp (R12 fix).
            if (ch + NSLOT < nch) {
                if (warp == 0) {
                    BAR_SYNC(1 + lslot);           // all consumers done
                    if (tid == 0) {
                        issue_chunk(ring_u32 + p_slot * CHUNK_B, mba[p_slot],
                                    logits, labels, p_tile, p_k);
                        if (++p_k == NCHPT) { p_k = 0; p_tile += NBLK; }
                        if (++p_slot == NSLOT) p_slot = 0;
                    }
                } else {
                    BAR_ARRIVE(1 + lslot);
                }
            }
            ch++;
            if (++lslot == NSLOT) { lslot = 0; lphase ^= 1; }
        }

        // ---- bin loop (registers + smem hist only) ----
        float invNa = rcp_fast(sa) * (float)NBINS;
        float invNb = rcp_fast(sb) * (float)NBINS;
        uint32_t inv2;
        asm("cvt.rn.f16x2.f32 %0,%1,%2;" : "=r"(inv2) : "f"(invNb), "f"(invNa));

        uint32_t bax = H_MAG, bay = H_MAG;
#pragma unroll
        for (int c = 0; c < NCLS; c++) {
            uint32_t b2;
            asm("fma.rn.f16x2 %0,%1,%2,%3;"
                : "=r"(b2) : "r"(eb[c]), "r"(inv2), "r"(MG16));
            uint32_t ra = b2 & 0xFFFFu;
            uint32_t rb = b2 >> 16;
            bax = (c == lab.x) ? ra : bax;
            bay = (c == lab.y) ? rb : bay;
            if (ra >= H_CUT)
                atomicAdd(&sh[c * NBINS + (ra - H_MAG)], 1u);
            if (rb >= H_CUT)
                atomicAdd(&sh[c * NBINS + (rb - H_MAG)], 1u);
        }
        int bfx = min((int)(NBINS - (bax - H_MAG)), NBINS - 1);
        atomicAdd(&sh[lab.x * NBINS + bfx], 0x10001u);
        int bfy = min((int)(NBINS - (bay - H_MAG)), NBINS - 1);
        atomicAdd(&sh[lab.y * NBINS + bfy], 0x10001u);
    }
    __syncthreads();

    uint4* dst = (uint4*)(g_part + (size_t)bid * (NCLS * NBINS));
    const uint4* src = (const uint4*)sh;
    for (int i = tid; i < NCLS * NBINS / 4; i += NTHR_H) dst[i] = src[i];
}

// Full-chip slice reduction: 76 blocks x 256 thr (4864 final bins).
__global__ __launch_bounds__(256) void reduce_kernel() {
    int base = blockIdx.x * 64;
    int t = threadIdx.x;
    int bin = t & 63;
    int g   = t >> 6;                      // 0..3, 37 slices each

    __shared__ uint32_t sc[64], sf[64];
    if (t < 64) { sc[t] = 0; sf[t] = 0; }
    __syncthreads();

    const uint32_t* p = g_part + base + bin;
    uint32_t cs = 0, fs = 0;
#pragma unroll 8
    for (int s = g * 37; s < g * 37 + 37; s++) {
        uint32_t v = __ldg(p + (size_t)s * (NCLS * NBINS));
        cs += v & 0xFFFFu;
        fs += v >> 16;
    }
    if (cs | fs) {
        atomicAdd(&sc[bin], cs);
        atomicAdd(&sf[bin], fs);
    }
    __syncthreads();
    if (t < 64) {
        g_cnt[base + t] = sc[t];
        g_fg [base + t] = sf[t];
    }
}

// One block per class, 256 threads (one per bin): mirror-correct, shuffle
// scan over descending ranks, closed-form Lovasz contribution.
__global__ __launch_bounds__(256) void scan_kernel(float* __restrict__ d_out) {
    int t = threadIdx.x;
    int c = blockIdx.x;

    __shared__ uint32_t wc[8], wf[8];
    __shared__ float    s_red[8];
    __shared__ float    s_totf;

    int b = (NBINS - 1) - t;
    uint32_t n = g_cnt[c * NBINS + b];
    uint32_t f = g_fg [c * NBINS + b];
    if (b >= CUTBIN) n -= g_fg[c * NBINS + (NBINS - b)];

    uint32_t ic = n, fc = f;
    int lane = t & 31, warp = t >> 5;      // 8 warps
#pragma unroll
    for (int d = 1; d < 32; d <<= 1) {
        uint32_t pc = __shfl_up_sync(0xffffffffu, ic, d);
        uint32_t pf = __shfl_up_sync(0xffffffffu, fc, d);
        if (lane >= d) { ic += pc; fc += pf; }
    }
    if (lane == 31) { wc[warp] = ic; wf[warp] = fc; }
    __syncthreads();

    if (t < 32) {
        uint32_t vc = (t < 8) ? wc[t] : 0;
        uint32_t vf = (t < 8) ? wf[t] : 0;
        uint32_t sc2 = vc, sf2 = vf;
#pragma unroll
        for (int d = 1; d < 32; d <<= 1) {
            uint32_t pc = __shfl_up_sync(0xffffffffu, sc2, d);
            uint32_t pf = __shfl_up_sync(0xffffffffu, sf2, d);
            if (t >= d) { sc2 += pc; sf2 += pf; }
        }
        if (t < 8) { wc[t] = sc2 - vc; wf[t] = sf2 - vf; }
        if (t == 7) s_totf = (float)sf2;
    }
    __syncthreads();

    float acc = 0.0f;
    if (n) {
        float gts = s_totf;
        float ccx = (float)(wc[warp] + (ic - n));
        float cfx = (float)(wf[warp] + (fc - f));
        float un0 = gts + ccx - cfx;
        float Jprev = (un0 > 0.0f) ? 1.0f - (gts - cfx) / un0 : 0.0f;
        float cci = ccx + (float)n;
        float cfi = cfx + (float)f;
        float un  = gts + cci - cfi;
        float J   = 1.0f - (gts - cfi) / un;
        acc = (float)b * (1.0f / (float)NBINS) * (J - Jprev);
    }

#pragma unroll
    for (int d = 16; d > 0; d >>= 1)
        acc += __shfl_down_sync(0xffffffffu, acc, d);
    if (lane == 0) s_red[warp] = acc;
    __syncthreads();
    if (t == 0) {
        float s = 0.0f;
#pragma unroll
        for (int i = 0; i < 8; i++) s += s_red[i];
        atomicAdd(d_out, s * (1.0f / (float)NCLS));
    }
}

extern "C" void kernel_launch(void* const* d_in, const int* in_sizes, int n_in,
                              void* d_out, int out_size) {
    const float* logits = (const float*)d_in[0];
    const int*   labels = (const int*)d_in[1];
    float* out = (float*)d_out;
    (void)in_sizes; (void)n_in; (void)out_size;

    static bool configured = false;
    if (!configured) {
        cudaFuncSetAttribute(hist_kernel,
                             cudaFuncAttributeMaxDynamicSharedMemorySize,
                             SMEM_TOTAL);
        configured = true;
    }

    hist_kernel<<<NBLK, NTHR_H, SMEM_TOTAL>>>(logits, labels, out);
    reduce_kernel<<<NCLS * NBINS / 64, 256>>>();
    scan_kernel<<<NCLS, 256>>>(out);
}

// round 15
// speedup vs baseline: 1.0871x; 1.0871x over previous
#include <cuda_runtime.h>
#include <stdint.h>

// Lovasz-Softmax, N=8, C=19, H=W=512.
// R14: revert to R10 architecture (independent per-warp LDG streams beat
// both pipeline variants R11/R13). Changes vs R10:
// (a) prefetch.global.L2 of the NEXT grid-stride iteration's 20 rows
//     (zero registers, ~26 issue slots) -> next LDGs are L2 hits (234 vs
//     577 cyc), halving the dominant long-scoreboard stall;
// (b) NBINS 512->256 (R13 bounded the precision cost at 1.3e-5): halves
//     hist zero/flush and the reduce kernel's traffic.

#define NCLS   19
#define NBINS  256
#define CUTBIN 64                  // drop bg entries with e < 1/4
#define HWSZ   (512 * 512)
#define NPIX   (8 * HWSZ)
#define NBLK   148
#define NTHR_H 1024

#define H_MAG  0x6600u             // fp16 bits of 1536.0 (1.5*2^10)
#define H_MAG2 0x66006600u
#define H_CUT  (H_MAG + CUTBIN)

#define F_L2E  1.4426950408889634f
#define F_MG   12582912.0f         // 1.5 * 2^23
#define F_C4   9.61812910e-3f
#define F_C3   5.55041087e-2f
#define F_C2   2.40226507e-1f
#define F_C1   6.93147181e-1f

typedef unsigned long long u64;

// Per-block partial histograms (packed cnt low16 | fg high16). ~2.9 MB.
__device__ uint32_t g_part[NBLK * NCLS * NBINS];
__device__ uint32_t g_cnt[NCLS * NBINS];
__device__ uint32_t g_fg [NCLS * NBINS];

// ---- packed f32x2 helpers (PTX-only) ----
__device__ __forceinline__ u64 pk(float a, float b) {
    u64 r; asm("mov.b64 %0,{%1,%2};" : "=l"(r) : "f"(a), "f"(b)); return r;
}
__device__ __forceinline__ void upk(u64 v, float& a, float& b) {
    asm("mov.b64 {%0,%1},%2;" : "=f"(a), "=f"(b) : "l"(v));
}
__device__ __forceinline__ u64 f2fma(u64 a, u64 b, u64 c) {
    u64 r; asm("fma.rn.f32x2 %0,%1,%2,%3;" : "=l"(r) : "l"(a), "l"(b), "l"(c));
    return r;
}
__device__ __forceinline__ u64 dup2(float a) { return pk(a, a); }
__device__ __forceinline__ float rcp_fast(float x) {
    float r; asm("rcp.approx.f32 %0,%1;" : "=f"(r) : "f"(x)); return r;
}
__device__ __forceinline__ void pf_l2(const void* p) {
    asm volatile("prefetch.global.L2 [%0];" :: "l"(p));
}

// Scalar exp replicating the packed pipeline op-for-op (bit-identical f32).
__device__ __forceinline__ float exp_mirror(float x) {
    float fm = fmaf(x, F_L2E, F_MG);
    float nf = fmaf(fm, -1.0f, F_MG);              // MG - fm = -round(t)
    float f  = fmaf(x, F_L2E, nf);
    float r  = fmaf(F_C4, f, F_C3);
    r = fmaf(r, f, F_C2);
    r = fmaf(r, f, F_C1);
    r = fmaf(r, f, 1.0f);
    return __int_as_float(__float_as_int(r) +
                          __float_as_int(fm) * 8388608);
}

extern __shared__ uint32_t sh[];   // [NCLS*NBINS + 64] (~19.7 KB)

__global__ __launch_bounds__(NTHR_H, 1) void hist_kernel(
    const float* __restrict__ logits, const int* __restrict__ labels,
    float* __restrict__ d_out) {
    int tid = threadIdx.x;
    if (blockIdx.x == 0 && tid == 0) *d_out = 0.0f;
    {
        uint4 z = make_uint4(0, 0, 0, 0);
        uint4* s4 = (uint4*)sh;
        for (int i = tid; i < (NCLS * NBINS + 64) / 4; i += NTHR_H) s4[i] = z;
    }
    __syncthreads();

    const u64 LOG2E = dup2(F_L2E);
    const u64 MG    = dup2(F_MG);
    const u64 NONE  = dup2(-1.0f);
    const u64 C4 = dup2(F_C4);
    const u64 C3 = dup2(F_C3);
    const u64 C2 = dup2(F_C2);
    const u64 C1 = dup2(F_C1);
    const u64 C0 = dup2(1.0f);
    const uint32_t MG16 = H_MAG2;

    const int NELEM  = NPIX / 2;     // float2 pixel pairs
    const int STRIDE = NBLK * NTHR_H;
    for (int q = blockIdx.x * NTHR_H + tid; q < NELEM; q += STRIDE) {
        int p0 = q * 2;
        int n  = p0 >> 18;
        int hw = p0 & (HWSZ - 1);
        const u64* base =
            (const u64*)(logits + (size_t)n * NCLS * HWSZ + hw);

        // Prefetch NEXT iteration's rows into L2 (zero registers consumed;
        // lead time ~1 iteration >> DRAM latency).
        {
            int qn = q + STRIDE;
            if (qn < NELEM) {
                int pn  = qn * 2;
                int nn  = pn >> 18;
                int hwn = pn & (HWSZ - 1);
                const char* bn =
                    (const char*)(logits + (size_t)nn * NCLS * HWSZ + hwn);
#pragma unroll
                for (int c = 0; c < NCLS; c++)
                    pf_l2(bn + (size_t)c * (HWSZ * 4));
                pf_l2(labels + pn);
            }
        }

        uint32_t eb[NCLS];         // fp16x2: lo = pixel a, hi = pixel b
        float sa = 0.0f, sb = 0.0f;
#pragma unroll
        for (int c = 0; c < NCLS; c++) {
            u64 xv = base[c * (HWSZ / 2)];         // LDG.64 packed pair
            u64 fm = f2fma(xv, LOG2E, MG);         // t + magic
            u64 nf = f2fma(fm, NONE, MG);          // MG - fm = -round(t)
            u64 f  = f2fma(xv, LOG2E, nf);         // frac in [-0.5, 0.5]
            u64 r  = f2fma(C4, f, C3);
            r = f2fma(r, f, C2);
            r = f2fma(r, f, C1);
            r = f2fma(r, f, C0);
            float fm0, fm1, r0, r1;
            upk(fm, fm0, fm1);
            upk(r, r0, r1);
            // 2^i scale as one IMAD per lane: bits += fm_bits * 2^23
            float e0 = __int_as_float(__float_as_int(r0) +
                                      __float_as_int(fm0) * 8388608);
            float e1 = __int_as_float(__float_as_int(r1) +
                                      __float_as_int(fm1) * 8388608);
            sa += e0;
            sb += e1;
            uint32_t w;            // lo = e0 (pixel a)
            asm("cvt.rn.f16x2.f32 %0,%1,%2;" : "=r"(w) : "f"(e1), "f"(e0));
            eb[c] = w;
        }
        float invNa = rcp_fast(sa) * (float)NBINS;
        float invNb = rcp_fast(sb) * (float)NBINS;
        uint32_t inv2;             // lo = pixel a
        asm("cvt.rn.f16x2.f32 %0,%1,%2;" : "=r"(inv2) : "f"(invNb), "f"(invNa));
        int2 lab = *(const int2*)(labels + p0);

#pragma unroll
        for (int c = 0; c < NCLS; c++) {
            uint32_t b2;           // both pixels' bins in one HFMA2
            asm("fma.rn.f16x2 %0,%1,%2,%3;"
                : "=r"(b2) : "r"(eb[c]), "r"(inv2), "r"(MG16));
            uint32_t ra = b2 & 0xFFFFu;
            uint32_t rb = b2 >> 16;
            // unconditional for all classes (spurious label-class count
            // corrected in scan via the mirror identity)
            if (ra >= H_CUT)
                atomicAdd(&sh[c * NBINS + (ra - H_MAG)], 1u);
            if (rb >= H_CUT)
                atomicAdd(&sh[c * NBINS + (rb - H_MAG)], 1u);
        }

        // Label bins via L1-hot gather + bit-exact scalar recompute.
        {
            float xa, xb, dumm;
            u64 va = base[lab.x * (HWSZ / 2)];     // L1 hit (just loaded)
            u64 vb = base[lab.y * (HWSZ / 2)];
            upk(va, xa, dumm);                     // pixel a = lo
            upk(vb, dumm, xb);                     // pixel b = hi
            float ea  = exp_mirror(xa);
            float ebv = exp_mirror(xb);
            uint32_t el2;                          // lo = pixel a
            asm("cvt.rn.f16x2.f32 %0,%1,%2;" : "=r"(el2) : "f"(ebv), "f"(ea));
            uint32_t bl2;
            asm("fma.rn.f16x2 %0,%1,%2,%3;"
                : "=r"(bl2) : "r"(el2), "r"(inv2), "r"(MG16));
            uint32_t bax = bl2 & 0xFFFFu;
            uint32_t bay = bl2 >> 16;
            // fg entries: bin = NBINS - b_label (exact mirror)
            int bfx = min((int)(NBINS - (bax - H_MAG)), NBINS - 1);
            atomicAdd(&sh[lab.x * NBINS + bfx], 0x10001u);
            int bfy = min((int)(NBINS - (bay - H_MAG)), NBINS - 1);
            atomicAdd(&sh[lab.y * NBINS + bfy], 0x10001u);
        }
    }
    __syncthreads();

    uint4* dst = (uint4*)(g_part + (size_t)blockIdx.x * (NCLS * NBINS));
    const uint4* src = (const uint4*)sh;
    for (int i = tid; i < NCLS * NBINS / 4; i += NTHR_H) dst[i] = src[i];
}

// Full-chip slice reduction: 76 blocks x 256 thr (4864 final bins).
__global__ __launch_bounds__(256) void reduce_kernel() {
    int base = blockIdx.x * 64;
    int t = threadIdx.x;
    int bin = t & 63;
    int g   = t >> 6;                      // 0..3, 37 slices each

    __shared__ uint32_t sc[64], sf[64];
    if (t < 64) { sc[t] = 0; sf[t] = 0; }
    __syncthreads();

    const uint32_t* p = g_part + base + bin;
    uint32_t cs = 0, fs = 0;
#pragma unroll 8
    for (int s = g * 37; s < g * 37 + 37; s++) {
        uint32_t v = __ldg(p + (size_t)s * (NCLS * NBINS));
        cs += v & 0xFFFFu;
        fs += v >> 16;
    }
    if (cs | fs) {
        atomicAdd(&sc[bin], cs);
        atomicAdd(&sf[bin], fs);
    }
    __syncthreads();
    if (t < 64) {
        g_cnt[base + t] = sc[t];
        g_fg [base + t] = sf[t];
    }
}

// One block per class, 256 threads (one per bin): mirror-correct, shuffle
// scan over descending ranks, closed-form Lovasz contribution.
__global__ __launch_bounds__(256) void scan_kernel(float* __restrict__ d_out) {
    int t = threadIdx.x;
    int c = blockIdx.x;

    __shared__ uint32_t wc[8], wf[8];
    __shared__ float    s_red[8];
    __shared__ float    s_totf;

    int b = (NBINS - 1) - t;
    uint32_t n = g_cnt[c * NBINS + b];
    uint32_t f = g_fg [c * NBINS + b];
    if (b >= CUTBIN) n -= g_fg[c * NBINS + (NBINS - b)];

    uint32_t ic = n, fc = f;
    int lane = t & 31, warp = t >> 5;      // 8 warps
#pragma unroll
    for (int d = 1; d < 32; d <<= 1) {
        uint32_t pc = __shfl_up_sync(0xffffffffu, ic, d);
        uint32_t pf = __shfl_up_sync(0xffffffffu, fc, d);
        if (lane >= d) { ic += pc; fc += pf; }
    }
    if (lane == 31) { wc[warp] = ic; wf[warp] = fc; }
    __syncthreads();

    if (t < 32) {
        uint32_t vc = (t < 8) ? wc[t] : 0;
        uint32_t vf = (t < 8) ? wf[t] : 0;
        uint32_t sc2 = vc, sf2 = vf;
#pragma unroll
        for (int d = 1; d < 32; d <<= 1) {
            uint32_t pc = __shfl_up_sync(0xffffffffu, sc2, d);
            uint32_t pf = __shfl_up_sync(0xffffffffu, sf2, d);
            if (t >= d) { sc2 += pc; sf2 += pf; }
        }
        if (t < 8) { wc[t] = sc2 - vc; wf[t] = sf2 - vf; }
        if (t == 7) s_totf = (float)sf2;
    }
    __syncthreads();

    float acc = 0.0f;
    if (n) {
        float gts = s_totf;
        float ccx = (float)(wc[warp] + (ic - n));
        float cfx = (float)(wf[warp] + (fc - f));
        float un0 = gts + ccx - cfx;
        float Jprev = (un0 > 0.0f) ? 1.0f - (gts - cfx) / un0 : 0.0f;
        float cci = ccx + (float)n;
        float cfi = cfx + (float)f;
        float un  = gts + cci - cfi;
        float J   = 1.0f - (gts - cfi) / un;
        acc = (float)b * (1.0f / (float)NBINS) * (J - Jprev);
    }

#pragma unroll
    for (int d = 16; d > 0; d >>= 1)
        acc += __shfl_down_sync(0xffffffffu, acc, d);
    if (lane == 0) s_red[warp] = acc;
    __syncthreads();
    if (t == 0) {
        float s = 0.0f;
#pragma unroll
        for (int i = 0; i < 8; i++) s += s_red[i];
        atomicAdd(d_out, s * (1.0f / (float)NCLS));
    }
}

extern "C" void kernel_launch(void* const* d_in, const int* in_sizes, int n_in,
                              void* d_out, int out_size) {
    const float* logits = (const float*)d_in[0];
    const int*   labels = (const int*)d_in[1];
    float* out = (float*)d_out;
    (void)in_sizes; (void)n_in; (void)out_size;

    static bool configured = false;
    if (!configured) {
        cudaFuncSetAttribute(hist_kernel,
                             cudaFuncAttributeMaxDynamicSharedMemorySize,
                             (NCLS * NBINS + 64) * sizeof(uint32_t));
        configured = true;
    }

    hist_kernel<<<NBLK, NTHR_H, (NCLS * NBINS + 64) * sizeof(uint32_t)>>>(
        logits, labels, out);
    reduce_kernel<<<NCLS * NBINS / 64, 256>>>();
    scan_kernel<<<NCLS, 256>>>(out);
}

// round 16
// speedup vs baseline: 1.2037x; 1.1073x over previous
#include <cuda_runtime.h>
#include <stdint.h>

// Lovasz-Softmax, N=8, C=19, H=W=512.
// R15: recombine the measured winners. R14 isolated: prefetch HURT hist
// (-3us: issue slots + L2 pollution at 160MB working set), NBINS=256 helped
// the tail (-2us). So: R10 hist (no prefetch) + NBINS=256 tail + packed
// f32x2 sum accumulation (-19 instr/pair).

#define NCLS   19
#define NBINS  256
#define CUTBIN 64                  // drop bg entries with e < 1/4
#define HWSZ   (512 * 512)
#define NPIX   (8 * HWSZ)
#define NBLK   148
#define NTHR_H 1024

#define H_MAG  0x6600u             // fp16 bits of 1536.0 (1.5*2^10)
#define H_MAG2 0x66006600u
#define H_CUT  (H_MAG + CUTBIN)

#define F_L2E  1.4426950408889634f
#define F_MG   12582912.0f         // 1.5 * 2^23
#define F_C4   9.61812910e-3f
#define F_C3   5.55041087e-2f
#define F_C2   2.40226507e-1f
#define F_C1   6.93147181e-1f

typedef unsigned long long u64;

// Per-block partial histograms (packed cnt low16 | fg high16). ~2.9 MB.
__device__ uint32_t g_part[NBLK * NCLS * NBINS];
__device__ uint32_t g_cnt[NCLS * NBINS];
__device__ uint32_t g_fg [NCLS * NBINS];

// ---- packed f32x2 helpers (PTX-only) ----
__device__ __forceinline__ u64 pk(float a, float b) {
    u64 r; asm("mov.b64 %0,{%1,%2};" : "=l"(r) : "f"(a), "f"(b)); return r;
}
__device__ __forceinline__ void upk(u64 v, float& a, float& b) {
    asm("mov.b64 {%0,%1},%2;" : "=f"(a), "=f"(b) : "l"(v));
}
__device__ __forceinline__ u64 f2fma(u64 a, u64 b, u64 c) {
    u64 r; asm("fma.rn.f32x2 %0,%1,%2,%3;" : "=l"(r) : "l"(a), "l"(b), "l"(c));
    return r;
}
__device__ __forceinline__ u64 dup2(float a) { return pk(a, a); }
__device__ __forceinline__ float rcp_fast(float x) {
    float r; asm("rcp.approx.f32 %0,%1;" : "=f"(r) : "f"(x)); return r;
}

// Scalar exp replicating the packed pipeline op-for-op (bit-identical f32).
__device__ __forceinline__ float exp_mirror(float x) {
    float fm = fmaf(x, F_L2E, F_MG);
    float nf = fmaf(fm, -1.0f, F_MG);              // MG - fm = -round(t)
    float f  = fmaf(x, F_L2E, nf);
    float r  = fmaf(F_C4, f, F_C3);
    r = fmaf(r, f, F_C2);
    r = fmaf(r, f, F_C1);
    r = fmaf(r, f, 1.0f);
    return __int_as_float(__float_as_int(r) +
                          __float_as_int(fm) * 8388608);
}

extern __shared__ uint32_t sh[];   // [NCLS*NBINS + 64] (~19.7 KB)

__global__ __launch_bounds__(NTHR_H, 1) void hist_kernel(
    const float* __restrict__ logits, const int* __restrict__ labels,
    float* __restrict__ d_out) {
    int tid = threadIdx.x;
    if (blockIdx.x == 0 && tid == 0) *d_out = 0.0f;
    {
        uint4 z = make_uint4(0, 0, 0, 0);
        uint4* s4 = (uint4*)sh;
        for (int i = tid; i < (NCLS * NBINS + 64) / 4; i += NTHR_H) s4[i] = z;
    }
    __syncthreads();

    const u64 LOG2E = dup2(F_L2E);
    const u64 MG    = dup2(F_MG);
    const u64 NONE  = dup2(-1.0f);
    const u64 C4 = dup2(F_C4);
    const u64 C3 = dup2(F_C3);
    const u64 C2 = dup2(F_C2);
    const u64 C1 = dup2(F_C1);
    const u64 C0 = dup2(1.0f);
    const uint32_t MG16 = H_MAG2;

    const int NELEM  = NPIX / 2;     // float2 pixel pairs
    const int STRIDE = NBLK * NTHR_H;
    for (int q = blockIdx.x * NTHR_H + tid; q < NELEM; q += STRIDE) {
        int p0 = q * 2;
        int n  = p0 >> 18;
        int hw = p0 & (HWSZ - 1);
        const u64* base =
            (const u64*)(logits + (size_t)n * NCLS * HWSZ + hw);

        uint32_t eb[NCLS];         // fp16x2: lo = pixel a, hi = pixel b
        u64 sum2 = pk(0.0f, 0.0f);
#pragma unroll
        for (int c = 0; c < NCLS; c++) {
            u64 xv = base[c * (HWSZ / 2)];         // LDG.64 packed pair
            u64 fm = f2fma(xv, LOG2E, MG);         // t + magic
            u64 nf = f2fma(fm, NONE, MG);          // MG - fm = -round(t)
            u64 f  = f2fma(xv, LOG2E, nf);         // frac in [-0.5, 0.5]
            u64 r  = f2fma(C4, f, C3);
            r = f2fma(r, f, C2);
            r = f2fma(r, f, C1);
            r = f2fma(r, f, C0);
            float fm0, fm1, r0, r1;
            upk(fm, fm0, fm1);
            upk(r, r0, r1);
            // 2^i scale as one IMAD per lane: bits += fm_bits * 2^23
            float e0 = __int_as_float(__float_as_int(r0) +
                                      __float_as_int(fm0) * 8388608);
            float e1 = __int_as_float(__float_as_int(r1) +
                                      __float_as_int(fm1) * 8388608);
            sum2 = f2fma(pk(e0, e1), C0, sum2);    // packed accumulate
            uint32_t w;            // lo = e0 (pixel a)
            asm("cvt.rn.f16x2.f32 %0,%1,%2;" : "=r"(w) : "f"(e1), "f"(e0));
            eb[c] = w;
        }
        float sa, sb;
        upk(sum2, sa, sb);
        float invNa = rcp_fast(sa) * (float)NBINS;
        float invNb = rcp_fast(sb) * (float)NBINS;
        uint32_t inv2;             // lo = pixel a
        asm("cvt.rn.f16x2.f32 %0,%1,%2;" : "=r"(inv2) : "f"(invNb), "f"(invNa));
        int2 lab = *(const int2*)(labels + p0);

#pragma unroll
        for (int c = 0; c < NCLS; c++) {
            uint32_t b2;           // both pixels' bins in one HFMA2
            asm("fma.rn.f16x2 %0,%1,%2,%3;"
                : "=r"(b2) : "r"(eb[c]), "r"(inv2), "r"(MG16));
            uint32_t ra = b2 & 0xFFFFu;
            uint32_t rb = b2 >> 16;
            // unconditional for all classes (spurious label-class count
            // corrected in scan via the mirror identity)
            if (ra >= H_CUT)
                atomicAdd(&sh[c * NBINS + (ra - H_MAG)], 1u);
            if (rb >= H_CUT)
                atomicAdd(&sh[c * NBINS + (rb - H_MAG)], 1u);
        }

        // Label bins via L1-hot gather + bit-exact scalar recompute.
        {
            float xa, xb, dumm;
            u64 va = base[lab.x * (HWSZ / 2)];     // L1 hit (just loaded)
            u64 vb = base[lab.y * (HWSZ / 2)];
            upk(va, xa, dumm);                     // pixel a = lo
            upk(vb, dumm, xb);                     // pixel b = hi
            float ea  = exp_mirror(xa);
            float ebv = exp_mirror(xb);
            uint32_t el2;                          // lo = pixel a
            asm("cvt.rn.f16x2.f32 %0,%1,%2;" : "=r"(el2) : "f"(ebv), "f"(ea));
            uint32_t bl2;
            asm("fma.rn.f16x2 %0,%1,%2,%3;"
                : "=r"(bl2) : "r"(el2), "r"(inv2), "r"(MG16));
            uint32_t bax = bl2 & 0xFFFFu;
            uint32_t bay = bl2 >> 16;
            // fg entries: bin = NBINS - b_label (exact mirror)
            int bfx = min((int)(NBINS - (bax - H_MAG)), NBINS - 1);
            atomicAdd(&sh[lab.x * NBINS + bfx], 0x10001u);
            int bfy = min((int)(NBINS - (bay - H_MAG)), NBINS - 1);
            atomicAdd(&sh[lab.y * NBINS + bfy], 0x10001u);
        }
    }
    __syncthreads();

    uint4* dst = (uint4*)(g_part + (size_t)blockIdx.x * (NCLS * NBINS));
    const uint4* src = (const uint4*)sh;
    for (int i = tid; i < NCLS * NBINS / 4; i += NTHR_H) dst[i] = src[i];
}

// Full-chip slice reduction: 76 blocks x 256 thr (4864 final bins).
__global__ __launch_bounds__(256) void reduce_kernel() {
    int base = blockIdx.x * 64;
    int t = threadIdx.x;
    int bin = t & 63;
    int g   = t >> 6;                      // 0..3, 37 slices each

    __shared__ uint32_t sc[64], sf[64];
    if (t < 64) { sc[t] = 0; sf[t] = 0; }
    __syncthreads();

    const uint32_t* p = g_part + base + bin;
    uint32_t cs = 0, fs = 0;
#pragma unroll 8
    for (int s = g * 37; s < g * 37 + 37; s++) {
        uint32_t v = __ldg(p + (size_t)s * (NCLS * NBINS));
        cs += v & 0xFFFFu;
        fs += v >> 16;
    }
    if (cs | fs) {
        atomicAdd(&sc[bin], cs);
        atomicAdd(&sf[bin], fs);
    }
    __syncthreads();
    if (t < 64) {
        g_cnt[base + t] = sc[t];
        g_fg [base + t] = sf[t];
    }
}

// One block per class, 256 threads (one per bin): mirror-correct, shuffle
// scan over descending ranks, closed-form Lovasz contribution.
__global__ __launch_bounds__(256) void scan_kernel(float* __restrict__ d_out) {
    int t = threadIdx.x;
    int c = blockIdx.x;

    __shared__ uint32_t wc[8], wf[8];
    __shared__ float    s_red[8];
    __shared__ float    s_totf;

    int b = (NBINS - 1) - t;
    uint32_t n = g_cnt[c * NBINS + b];
    uint32_t f = g_fg [c * NBINS + b];
    if (b >= CUTBIN) n -= g_fg[c * NBINS + (NBINS - b)];

    uint32_t ic = n, fc = f;
    int lane = t & 31, warp = t >> 5;      // 8 warps
#pragma unroll
    for (int d = 1; d < 32; d <<= 1) {
        uint32_t pc = __shfl_up_sync(0xffffffffu, ic, d);
        uint32_t pf = __shfl_up_sync(0xffffffffu, fc, d);
        if (lane >= d) { ic += pc; fc += pf; }
    }
    if (lane == 31) { wc[warp] = ic; wf[warp] = fc; }
    __syncthreads();

    if (t < 32) {
        uint32_t vc = (t < 8) ? wc[t] : 0;
        uint32_t vf = (t < 8) ? wf[t] : 0;
        uint32_t sc2 = vc, sf2 = vf;
#pragma unroll
        for (int d = 1; d < 32; d <<= 1) {
            uint32_t pc = __shfl_up_sync(0xffffffffu, sc2, d);
            uint32_t pf = __shfl_up_sync(0xffffffffu, sf2, d);
            if (t >= d) { sc2 += pc; sf2 += pf; }
        }
        if (t < 8) { wc[t] = sc2 - vc; wf[t] = sf2 - vf; }
        if (t == 7) s_totf = (float)sf2;
    }
    __syncthreads();

    float acc = 0.0f;
    if (n) {
        float gts = s_totf;
        float ccx = (float)(wc[warp] + (ic - n));
        float cfx = (float)(wf[warp] + (fc - f));
        float un0 = gts + ccx - cfx;
        float Jprev = (un0 > 0.0f) ? 1.0f - (gts - cfx) / un0 : 0.0f;
        float cci = ccx + (float)n;
        float cfi = cfx + (float)f;
        float un  = gts + cci - cfi;
        float J   = 1.0f - (gts - cfi) / un;
        acc = (float)b * (1.0f / (float)NBINS) * (J - Jprev);
    }

#pragma unroll
    for (int d = 16; d > 0; d >>= 1)
        acc += __shfl_down_sync(0xffffffffu, acc, d);
    if (lane == 0) s_red[warp] = acc;
    __syncthreads();
    if (t == 0) {
        float s = 0.0f;
#pragma unroll
        for (int i = 0; i < 8; i++) s += s_red[i];
        atomicAdd(d_out, s * (1.0f / (float)NCLS));
    }
}

extern "C" void kernel_launch(void* const* d_in, const int* in_sizes, int n_in,
                              void* d_out, int out_size) {
    const float* logits = (const float*)d_in[0];
    const int*   labels = (const int*)d_in[1];
    float* out = (float*)d_out;
    (void)in_sizes; (void)n_in; (void)out_size;

    static bool configured = false;
    if (!configured) {
        cudaFuncSetAttribute(hist_kernel,
                             cudaFuncAttributeMaxDynamicSharedMemorySize,
                             (NCLS * NBINS + 64) * sizeof(uint32_t));
        configured = true;
    }

    hist_kernel<<<NBLK, NTHR_H, (NCLS * NBINS + 64) * sizeof(uint32_t)>>>(
        logits, labels, out);
    reduce_kernel<<<NCLS * NBINS / 64, 256>>>();
    scan_kernel<<<NCLS, 256>>>(out);
}